// round 2
// baseline (speedup 1.0000x reference)
#include <cuda_runtime.h>
#include <cstdint>

// Problem constants (from reference)
#define BB 1024
#define SS 512
#define TT 64

// ---------------- device scratch (no allocs allowed) ----------------
__device__ float4 g_E4[32 * 32];     // packed exp(transitions): (E[i][j], E[i+32][j], E[i][j+32], E[i+32][j+32])
__device__ float  g_ll[BB];          // per-batch log-likelihood

// ---------------- f32x2 helpers (inline PTX; ptxas won't emit FFMA2 itself) ----------------
__device__ __forceinline__ unsigned long long pack2(float lo, float hi) {
    unsigned long long r;
    asm("mov.b64 %0, {%1, %2};" : "=l"(r) : "f"(lo), "f"(hi));
    return r;
}
__device__ __forceinline__ void unpack2(unsigned long long v, float& lo, float& hi) {
    asm("mov.b64 {%0, %1}, %2;" : "=f"(lo), "=f"(hi) : "l"(v));
}
__device__ __forceinline__ unsigned long long fma2(unsigned long long a, unsigned long long b, unsigned long long c) {
    unsigned long long r;
    asm("fma.rn.f32x2 %0, %1, %2, %3;" : "=l"(r) : "l"(a), "l"(b), "l"(c));
    return r;
}
__device__ __forceinline__ unsigned long long add2(unsigned long long a, unsigned long long b) {
    unsigned long long r;
    asm("add.rn.f32x2 %0, %1, %2;" : "=l"(r) : "l"(a), "l"(b));
    return r;
}

// ---------------- prep: E = exp(transitions) packed, + copy transitions to output ----------------
__global__ void crf_prep_kernel(const float* __restrict__ trans, float* __restrict__ d_out, int out_size) {
    int idx = blockIdx.x * blockDim.x + threadIdx.x;   // 0..4095
    if (idx < 4096 && out_size >= 4097) {
        d_out[1 + idx] = trans[idx];
    }
    if (idx < 1024) {
        int ii = idx >> 5;     // 0..31
        int l  = idx & 31;     // 0..31
        float4 e;
        e.x = __expf(trans[ii * 64 + l]);
        e.y = __expf(trans[(ii + 32) * 64 + l]);
        e.z = __expf(trans[ii * 64 + l + 32]);
        e.w = __expf(trans[(ii + 32) * 64 + l + 32]);
        g_E4[idx] = e;
    }
}

// ---------------- main: 1 warp per batch ----------------
__global__ __launch_bounds__(128) void crf_main_kernel(
    const float* __restrict__ inputs,          // [B, S, T]
    const float* __restrict__ trans,           // [T, T]
    const unsigned char* __restrict__ masks,   // [B, S] (bool)
    const int* __restrict__ tags)              // [B, S]
{
    __shared__ float s_trans[64 * 64];                  // 16 KB (binary lookups; avoids L1 thrash from streaming x)
    __shared__ unsigned long long s_v[4][2][32];        // per-warp, double-buffered packed (v[i], v[i+32])

    const int w    = threadIdx.x >> 5;
    const int lane = threadIdx.x & 31;
    const int b    = blockIdx.x * 4 + w;

    // cooperative transitions load
    for (int i = threadIdx.x; i < 4096; i += 128) s_trans[i] = trans[i];
    __syncthreads();

    // E in registers: lane l owns columns l and l+32.
    // Ea[ii] = (E[ii][l],    E[ii+32][l]   )
    // Eb[ii] = (E[ii][l+32], E[ii+32][l+32])
    unsigned long long Ea[32], Eb[32];
#pragma unroll
    for (int ii = 0; ii < 32; ii++) {
        float4 e = g_E4[ii * 32 + lane];
        Ea[ii] = pack2(e.x, e.y);
        Eb[ii] = pack2(e.z, e.w);
    }

    const float* xb = inputs + (size_t)b * SS * TT;
    const unsigned FULL = 0xFFFFFFFFu;

    // s = 0
    float a0 = xb[lane];
    float a1 = xb[lane + 32];
    int t_prev = tags[b * SS];
    unsigned char mk0 = masks[b * SS];
    float sel0 = (t_prev < 32) ? a0 : a1;
    float u0 = __shfl_sync(FULL, sel0, t_prev & 31);
    float unary  = mk0 ? 0.0f : u0;
    float binary = 0.0f;

    // prefetch s = 1
    float xn0 = xb[TT + lane];
    float xn1 = xb[TT + lane + 32];
    int tn = tags[b * SS + 1];
    unsigned char mn = masks[b * SS + 1];

    for (int s = 1; s < SS; s++) {
        float x0 = xn0, x1 = xn1;
        int   t  = tn;
        unsigned char mk = mn;

        // prefetch next step (clamped — last iter re-reads 511, unused)
        int sp = (s + 1 < SS) ? (s + 1) : (SS - 1);
        xn0 = xb[sp * TT + lane];
        xn1 = xb[sp * TT + lane + 32];
        tn  = tags[b * SS + sp];
        mn  = masks[b * SS + sp];

        // max over alphas (warp butterfly over 64 values)
        float m = fmaxf(a0, a1);
#pragma unroll
        for (int off = 16; off > 0; off >>= 1)
            m = fmaxf(m, __shfl_xor_sync(FULL, m, off));

        // v = exp(alpha - m), packed (v[l], v[l+32]) into this warp's buffer
        float v0 = __expf(a0 - m);
        float v1 = __expf(a1 - m);
        const int buf = s & 1;
        s_v[w][buf][lane] = pack2(v0, v1);
        __syncwarp();

        // matvec: w[j] = sum_i v[i] * E[i][j], via f32x2 with (i, i+32) interleave
        const unsigned long long* vv = s_v[w][buf];
        unsigned long long A0 = 0ull, A1 = 0ull, B0 = 0ull, B1 = 0ull;
#pragma unroll
        for (int ii = 0; ii < 32; ii += 2) {
            unsigned long long va = vv[ii];
            A0 = fma2(va, Ea[ii], A0);
            B0 = fma2(va, Eb[ii], B0);
            unsigned long long vb = vv[ii + 1];
            A1 = fma2(vb, Ea[ii + 1], A1);
            B1 = fma2(vb, Eb[ii + 1], B1);
        }
        unsigned long long As = add2(A0, A1);
        unsigned long long Bs = add2(B0, B1);
        float p, q, r, u;
        unpack2(As, p, q);
        unpack2(Bs, r, u);
        float w0v = p + q;     // w[lane]
        float w1v = r + u;     // w[lane+32]

        float na0 = x0 + m + __logf(w0v);
        float na1 = x1 + m + __logf(w1v);

        // path score pieces for this step
        float selx = (t < 32) ? x0 : x1;              // t is warp-uniform
        float uv = __shfl_sync(FULL, selx, t & 31);
        float bv = s_trans[t_prev * 64 + t];

        if (!mk) {             // warp-uniform
            a0 = na0;
            a1 = na1;
            unary  += uv;
            binary += bv;
        }
        t_prev = t;
    }

    // log_norm = logsumexp(alphas)
    float m2 = fmaxf(a0, a1);
#pragma unroll
    for (int off = 16; off > 0; off >>= 1)
        m2 = fmaxf(m2, __shfl_xor_sync(FULL, m2, off));
    float sv = __expf(a0 - m2) + __expf(a1 - m2);
#pragma unroll
    for (int off = 16; off > 0; off >>= 1)
        sv += __shfl_xor_sync(FULL, sv, off);
    float log_norm = m2 + __logf(sv);

    if (lane == 0)
        g_ll[b] = unary + binary - log_norm;
}

// ---------------- deterministic reduction ----------------
__global__ void crf_reduce_kernel(float* __restrict__ d_out) {
    __shared__ double sm[256];
    int t = threadIdx.x;
    double s = 0.0;
    for (int i = t; i < BB; i += 256) s += (double)g_ll[i];
    sm[t] = s;
    __syncthreads();
    for (int off = 128; off > 0; off >>= 1) {
        if (t < off) sm[t] += sm[t + off];
        __syncthreads();
    }
    if (t == 0) d_out[0] = (float)(-sm[0] / (double)BB);
}

extern "C" void kernel_launch(void* const* d_in, const int* in_sizes, int n_in,
                              void* d_out, int out_size) {
    const float*         inputs = (const float*)d_in[0];
    const float*         trans  = (const float*)d_in[1];
    const unsigned char* masks  = (const unsigned char*)d_in[2];
    const int*           tags   = (const int*)d_in[3];
    float*               out    = (float*)d_out;

    crf_prep_kernel<<<8, 512>>>(trans, out, out_size);
    crf_main_kernel<<<256, 128>>>(inputs, trans, masks, tags);
    crf_reduce_kernel<<<1, 256>>>(out);
}

// round 3
// speedup vs baseline: 2.4936x; 2.4936x over previous
#include <cuda_runtime.h>
#include <cstdint>

// Problem constants (from reference)
#define BB 1024
#define SS 512
#define TT 64

// ---------------- device scratch (no allocs allowed) ----------------
__device__ float4 g_E4[32 * 32];     // packed exp(transitions): (E[i][j], E[i+32][j], E[i][j+32], E[i+32][j+32])
__device__ float  g_ll[BB];          // per-batch log-likelihood

// ---------------- f32x2 helpers (inline PTX; ptxas won't emit FFMA2 itself) ----------------
__device__ __forceinline__ unsigned long long pack2(float lo, float hi) {
    unsigned long long r;
    asm("mov.b64 %0, {%1, %2};" : "=l"(r) : "f"(lo), "f"(hi));
    return r;
}
__device__ __forceinline__ void unpack2(unsigned long long v, float& lo, float& hi) {
    asm("mov.b64 {%0, %1}, %2;" : "=f"(lo), "=f"(hi) : "l"(v));
}
__device__ __forceinline__ unsigned long long fma2(unsigned long long a, unsigned long long b, unsigned long long c) {
    unsigned long long r;
    asm("fma.rn.f32x2 %0, %1, %2, %3;" : "=l"(r) : "l"(a), "l"(b), "l"(c));
    return r;
}
__device__ __forceinline__ unsigned long long add2(unsigned long long a, unsigned long long b) {
    unsigned long long r;
    asm("add.rn.f32x2 %0, %1, %2;" : "=l"(r) : "l"(a), "l"(b));
    return r;
}

// ---------------- prep: E = exp(transitions) packed, + copy transitions to output ----------------
__global__ void crf_prep_kernel(const float* __restrict__ trans, float* __restrict__ d_out, int out_size) {
    int idx = blockIdx.x * blockDim.x + threadIdx.x;   // 0..4095
    if (idx < 4096 && out_size >= 4097) {
        d_out[1 + idx] = trans[idx];
    }
    if (idx < 1024) {
        int ii = idx >> 5;     // 0..31
        int l  = idx & 31;     // 0..31
        float4 e;
        e.x = __expf(trans[ii * 64 + l]);
        e.y = __expf(trans[(ii + 32) * 64 + l]);
        e.z = __expf(trans[ii * 64 + l + 32]);
        e.w = __expf(trans[(ii + 32) * 64 + l + 32]);
        g_E4[idx] = e;
    }
}

// One CRF forward step. Uses stale-by-one LSE shift m (off critical path).
// Free variables from enclosing scope: a0,a1,m_use,m_next,unary,binary,t_prev,
// s_v,w,lane,Ea,Eb,s_trans,FULL.
#define CRF_STEP(x0_, x1_, t_, mk_, par_)                                        \
    do {                                                                         \
        float m = m_use;                                                         \
        m_use = m_next;                                                          \
        float v0 = __expf(a0 - m);                                               \
        float v1 = __expf(a1 - m);                                               \
        const int buf_ = (par_) & 1;                                             \
        s_v[w][buf_][lane] = pack2(v0, v1);                                      \
        __syncwarp();                                                            \
        const unsigned long long* vv = s_v[w][buf_];                             \
        unsigned long long A0 = 0ull, A1 = 0ull, B0 = 0ull, B1 = 0ull;           \
        _Pragma("unroll")                                                        \
        for (int ii = 0; ii < 32; ii += 2) {                                     \
            unsigned long long va = vv[ii];                                      \
            A0 = fma2(va, Ea[ii], A0);                                           \
            B0 = fma2(va, Eb[ii], B0);                                           \
            unsigned long long vb = vv[ii + 1];                                  \
            A1 = fma2(vb, Ea[ii + 1], A1);                                       \
            B1 = fma2(vb, Eb[ii + 1], B1);                                       \
        }                                                                        \
        unsigned long long As = add2(A0, A1);                                    \
        unsigned long long Bs = add2(B0, B1);                                    \
        float p_, q_, r_, u_;                                                    \
        unpack2(As, p_, q_);                                                     \
        unpack2(Bs, r_, u_);                                                     \
        float na0 = (x0_) + (m + __logf(p_ + q_));                               \
        float na1 = (x1_) + (m + __logf(r_ + u_));                               \
        float selx = ((t_) < 32) ? (x0_) : (x1_);                                \
        float uv = __shfl_sync(FULL, selx, (t_) & 31);                           \
        float bv = s_trans[t_prev * 64 + (t_)];                                  \
        if (!(mk_)) {                                                            \
            a0 = na0; a1 = na1;                                                  \
            unary += uv; binary += bv;                                           \
        }                                                                        \
        t_prev = (t_);                                                           \
        m_next = __shfl_sync(FULL, a0, 0);                                       \
    } while (0)

// ---------------- main: 1 warp per batch, depth-4 x-prefetch pipeline ----------------
__global__ __launch_bounds__(128) void crf_main_kernel(
    const float* __restrict__ inputs,          // [B, S, T]
    const float* __restrict__ trans,           // [T, T]
    const unsigned char* __restrict__ masks,   // [B, S] (bool)
    const int* __restrict__ tags)              // [B, S]
{
    __shared__ float s_trans[64 * 64];                  // 16 KB (binary lookups)
    __shared__ unsigned long long s_v[4][2][32];        // per-warp, double-buffered packed (v[i], v[i+32])

    const int w    = threadIdx.x >> 5;
    const int lane = threadIdx.x & 31;
    const int b    = blockIdx.x * 4 + w;

    // cooperative transitions load
    for (int i = threadIdx.x; i < 4096; i += 128) s_trans[i] = trans[i];
    __syncthreads();

    // E in registers: lane l owns output columns l and l+32.
    unsigned long long Ea[32], Eb[32];
#pragma unroll
    for (int ii = 0; ii < 32; ii++) {
        float4 e = g_E4[ii * 32 + lane];
        Ea[ii] = pack2(e.x, e.y);
        Eb[ii] = pack2(e.z, e.w);
    }

    const float* xb = inputs + (size_t)b * SS * TT;
    const unsigned FULL = 0xFFFFFFFFu;

    // s = 0
    float a0 = xb[lane];
    float a1 = xb[lane + 32];
    int t_prev = tags[b * SS];
    unsigned char mk0 = masks[b * SS];
    float sel0 = (t_prev < 32) ? a0 : a1;
    float u0 = __shfl_sync(FULL, sel0, t_prev & 31);
    float unary  = mk0 ? 0.0f : u0;
    float binary = 0.0f;

    // LSE shift pipeline (stale-by-one broadcast of lane0 alpha)
    float m_next = __shfl_sync(FULL, a0, 0);
    float m_use  = m_next;

    // depth-4 prefetch queue for steps 1..4
    float q0[4], q1[4];
    int qt[4];
    unsigned char qm[4];
#pragma unroll
    for (int u = 0; u < 4; u++) {
        int sp = 1 + u;
        q0[u] = xb[sp * TT + lane];
        q1[u] = xb[sp * TT + lane + 32];
        qt[u] = tags[b * SS + sp];
        qm[u] = masks[b * SS + sp];
    }

    int s = 1;
    // main loop: 127 iterations -> steps 1..508; prefetch runs 4 ahead
    for (int it = 0; it < 127; it++, s += 4) {
#pragma unroll
        for (int u = 0; u < 4; u++) {
            float x0 = q0[u], x1 = q1[u];
            int t = qt[u];
            unsigned char mk = qm[u];

            int sp = s + u + 4;
            if (sp > SS - 1) sp = SS - 1;
            q0[u] = xb[sp * TT + lane];
            q1[u] = xb[sp * TT + lane + 32];
            qt[u] = tags[b * SS + sp];
            qm[u] = masks[b * SS + sp];

            CRF_STEP(x0, x1, t, mk, s + u);
        }
    }
    // epilogue: steps 509, 510, 511 (already in queue slots 0..2)
#pragma unroll
    for (int u = 0; u < 3; u++) {
        float x0 = q0[u], x1 = q1[u];
        int t = qt[u];
        unsigned char mk = qm[u];
        CRF_STEP(x0, x1, t, mk, s + u);
    }

    // log_norm = logsumexp(alphas) — exact max here (once, off the hot loop)
    float m2 = fmaxf(a0, a1);
#pragma unroll
    for (int off = 16; off > 0; off >>= 1)
        m2 = fmaxf(m2, __shfl_xor_sync(FULL, m2, off));
    float sv = __expf(a0 - m2) + __expf(a1 - m2);
#pragma unroll
    for (int off = 16; off > 0; off >>= 1)
        sv += __shfl_xor_sync(FULL, sv, off);
    float log_norm = m2 + __logf(sv);

    if (lane == 0)
        g_ll[b] = unary + binary - log_norm;
}

// ---------------- deterministic reduction ----------------
__global__ void crf_reduce_kernel(float* __restrict__ d_out) {
    __shared__ double sm[256];
    int t = threadIdx.x;
    double s = 0.0;
    for (int i = t; i < BB; i += 256) s += (double)g_ll[i];
    sm[t] = s;
    __syncthreads();
    for (int off = 128; off > 0; off >>= 1) {
        if (t < off) sm[t] += sm[t + off];
        __syncthreads();
    }
    if (t == 0) d_out[0] = (float)(-sm[0] / (double)BB);
}

extern "C" void kernel_launch(void* const* d_in, const int* in_sizes, int n_in,
                              void* d_out, int out_size) {
    const float*         inputs = (const float*)d_in[0];
    const float*         trans  = (const float*)d_in[1];
    const unsigned char* masks  = (const unsigned char*)d_in[2];
    const int*           tags   = (const int*)d_in[3];
    float*               out    = (float*)d_out;

    crf_prep_kernel<<<8, 512>>>(trans, out, out_size);
    crf_main_kernel<<<256, 128>>>(inputs, trans, masks, tags);
    crf_reduce_kernel<<<1, 256>>>(out);
}